// round 14
// baseline (speedup 1.0000x reference)
#include <cuda_runtime.h>
#include <cuda_fp16.h>
#include <math_constants.h>
#include <cstdint>

// ----------------------- problem constants -----------------------
#define N_SRC 8192
#define M_TGT 32768
#define D_DIM 64
#define BN 128
#define BM 256
#define NTILES (N_SRC / BN)         // 64
#define MCHUNKS (M_TGT / BM)        // 128
#define NUNITS (NTILES * MCHUNKS)   // 8192
#define NCTAS 296                   // 2 CTAs per SM
#define THREADS 256                 // 8 warps

// ----------------------- SMEM layout (per CTA: ~85 KB) -----------
#define SM_A       0                // 16384
#define SM_B       16384            // 2 x 32768 = 65536
#define SM_C       81920            // 2 x 1024
#define SM_MIN     83968            // 256 floats = 1024
#define SM_FLAG    84992            // 4
#define SM_MEANPSI 84996            // 4
#define SMEM_TOTAL 85056

// ----------------------- device scratch --------------------------
__device__ __half g_src_h[N_SRC * D_DIM];
__device__ __half g_tgt_h[M_TGT * D_DIM];
__device__ float  g_c[M_TGT];
__device__ float  g_sqsrc[N_SRC];
__device__ float  g_psipart[NCTAS];
__device__ int    g_partial[N_SRC];
__device__ int    g_cnt[NTILES];
__device__ int    g_exp[NTILES];
__device__ unsigned int g_bar;       // monotonic grid barrier

// ----------------------- helpers ---------------------------------
__device__ __forceinline__ uint32_t smem_u32(const void* p) {
    uint32_t a;
    asm("{ .reg .u64 t; cvta.to.shared.u64 t, %1; cvt.u32.u64 %0, t; }" : "=r"(a) : "l"(p));
    return a;
}
__device__ __forceinline__ uint32_t swz128(uint32_t off) { return off ^ ((off >> 3) & 0x70); }

#define CP_ASYNC16(dst, src) \
    asm volatile("cp.async.cg.shared.global [%0], [%1], 16;" :: "r"((uint32_t)(dst)), "l"(src) : "memory")
#define CP_COMMIT() asm volatile("cp.async.commit_group;" ::: "memory")
#define CP_WAIT0()  asm volatile("cp.async.wait_group 0;" ::: "memory")

#define LDSM_X4(r0, r1, r2, r3, addr) \
    asm volatile("ldmatrix.sync.aligned.m8n8.x4.shared.b16 {%0,%1,%2,%3}, [%4];" \
                 : "=r"(r0), "=r"(r1), "=r"(r2), "=r"(r3) : "r"(addr))

#define MMA16816(d, a, b0, b1) \
    asm volatile("mma.sync.aligned.m16n8k16.row.col.f32.f16.f16.f32 " \
                 "{%0,%1,%2,%3},{%4,%5,%6,%7},{%8,%9},{%0,%1,%2,%3};" \
                 : "+f"((d)[0]), "+f"((d)[1]), "+f"((d)[2]), "+f"((d)[3]) \
                 : "r"((a)[0]), "r"((a)[1]), "r"((a)[2]), "r"((a)[3]), "r"(b0), "r"(b1))

__device__ __forceinline__ void atomicMinF(int* addr, float v) {
    if (v >= 0.f) atomicMin(addr, __float_as_int(v));
    else          atomicMax((unsigned int*)addr, __float_as_uint(v));
}

// ----------------------- prep phase (in-kernel) -------------------
__device__ __forceinline__ void prep_phase(const float* __restrict__ src,
                                           const float* __restrict__ tgt,
                                           const float* __restrict__ psi,
                                           char* smem, int tid) {
    const int wid = tid >> 5, lane = tid & 31;
    const int gwarp = blockIdx.x * (THREADS / 32) + wid;
    const int nwarps = NCTAS * (THREADS / 32);      // 2368

    for (int row = gwarp; row < N_SRC + M_TGT; row += nwarps) {
        if (row < N_SRC) {
            float2 a = reinterpret_cast<const float2*>(src + (size_t)row * D_DIM)[lane];
            reinterpret_cast<__half2*>(g_src_h + (size_t)row * D_DIM)[lane] = __floats2half2_rn(a.x, a.y);
            float s = a.x * a.x + a.y * a.y;
#pragma unroll
            for (int o = 16; o > 0; o >>= 1) s += __shfl_xor_sync(0xffffffffu, s, o);
            if (lane == 0) g_sqsrc[row] = s;
        } else {
            int m = row - N_SRC;
            float2 a = reinterpret_cast<const float2*>(tgt + (size_t)m * D_DIM)[lane];
            reinterpret_cast<__half2*>(g_tgt_h + (size_t)m * D_DIM)[lane] = __floats2half2_rn(a.x, a.y);
            float s = a.x * a.x + a.y * a.y;
#pragma unroll
            for (int o = 16; o > 0; o >>= 1) s += __shfl_xor_sync(0xffffffffu, s, o);
            if (lane == 0) g_c[m] = s - psi[m];
        }
    }

    for (int n = blockIdx.x * THREADS + tid; n < N_SRC; n += NCTAS * THREADS)
        g_partial[n] = 0x7F800000;   // +inf

    if (blockIdx.x == 1 && tid < NTILES) {
        int nt = tid, cnt = 0;
        for (int cta = 0; cta < NCTAS; cta++) {
            int us = (int)(((long long)cta * NUNITS) / NCTAS);
            int ue = (int)(((long long)(cta + 1) * NUNITS) / NCTAS);
            if (us < (nt + 1) * MCHUNKS && ue > nt * MCHUNKS) cnt++;
        }
        g_exp[nt] = cnt;
        g_cnt[nt] = 0;
    }

    {
        float* red = reinterpret_cast<float*>(smem + SM_MIN);
        float s = 0.f;
        for (int i = blockIdx.x * THREADS + tid; i < M_TGT; i += NCTAS * THREADS) s += psi[i];
#pragma unroll
        for (int o = 16; o > 0; o >>= 1) s += __shfl_xor_sync(0xffffffffu, s, o);
        if (lane == 0) red[wid] = s;
        __syncthreads();
        if (tid < 32) {
            float v = (tid < THREADS / 32) ? red[tid] : 0.f;
#pragma unroll
            for (int o = 16; o > 0; o >>= 1) v += __shfl_xor_sync(0xffffffffu, v, o);
            if (tid == 0) g_psipart[blockIdx.x] = v;
        }
        __syncthreads();
    }
}

// monotonic grid barrier
__device__ __forceinline__ void grid_barrier(int tid) {
    __syncthreads();
    if (tid == 0) {
        __threadfence();
        unsigned int base = atomicAdd(&g_bar, 1u);
        unsigned int target = (base / NCTAS + 1u) * NCTAS;
        volatile unsigned int* p = &g_bar;
        while (*p < target) { __nanosleep(64); }
    }
    __syncthreads();
    __threadfence();
}

// ----------------------- main loop pieces -------------------------
__device__ __forceinline__ void load_B_chunk(uint32_t sb, int stage, int ch, int tid) {
    const __half* p = g_tgt_h + (size_t)ch * BM * D_DIM;
    uint32_t d = sb + SM_B + stage * 32768;
#pragma unroll
    for (int j = 0; j < 8; j++) {
        int idx = j * THREADS + tid;
        int row = idx >> 3, c8 = idx & 7;
        CP_ASYNC16(d + swz128(row * 128 + c8 * 16), p + row * D_DIM + c8 * 8);
    }
    if (tid < 64)
        CP_ASYNC16(sb + SM_C + stage * 1024 + tid * 16, g_c + (size_t)ch * BM + tid * 4);
}

__device__ __forceinline__ void load_A_tile(uint32_t sb, int nt, int tid) {
    const __half* p = g_src_h + (size_t)nt * BN * D_DIM;
#pragma unroll
    for (int j = 0; j < 4; j++) {
        int idx = j * THREADS + tid;
        int row = idx >> 3, c8 = idx & 7;
        CP_ASYNC16(sb + SM_A + swz128(row * 128 + c8 * 16), p + row * D_DIM + c8 * 8);
    }
}

__device__ __forceinline__ void load_A_frags(uint32_t sb, int wm, int lane, uint32_t a[2][4][4]) {
#pragma unroll
    for (int mt = 0; mt < 2; mt++)
#pragma unroll
        for (int ks = 0; ks < 4; ks++) {
            uint32_t row = wm * 32 + mt * 16 + (lane & 15);
            uint32_t kb = ks * 32 + ((lane >> 4) & 1) * 16;
            LDSM_X4(a[mt][ks][0], a[mt][ks][1], a[mt][ks][2], a[mt][ks][3],
                    sb + SM_A + swz128(row * 128 + kb));
        }
}

__device__ __forceinline__ void flush_and_finalize(char* smem, float minv[2][2], int nt,
                                                   int wm, int wn, int q, int e, int tid,
                                                   float* __restrict__ out) {
    float* smin = reinterpret_cast<float*>(smem + SM_MIN);
#pragma unroll
    for (int mt = 0; mt < 2; mt++)
#pragma unroll
        for (int h = 0; h < 2; h++) {
            float v = minv[mt][h];
            v = fminf(v, __shfl_xor_sync(0xffffffffu, v, 1));
            v = fminf(v, __shfl_xor_sync(0xffffffffu, v, 2));
            if (e == 0) smin[wn * 128 + wm * 32 + mt * 16 + h * 8 + q] = v;
        }
    __syncthreads();
    const int n0 = nt * BN;
    if (tid < 128) {
        float v = fminf(smin[tid], smin[128 + tid]);
        atomicMinF(&g_partial[n0 + tid], v);
    }
    __threadfence();
    __syncthreads();
    if (tid == 0) {
        int old = atomicAdd(&g_cnt[nt], 1);
        *reinterpret_cast<int*>(smem + SM_FLAG) = (old == g_exp[nt] - 1);
    }
    __syncthreads();
    if (*reinterpret_cast<int*>(smem + SM_FLAG) && tid < 128) {
        float mp = *reinterpret_cast<float*>(smem + SM_MEANPSI);
        int bits = atomicAdd(&g_partial[n0 + tid], 0);
        out[n0 + tid] = __int_as_float(bits) + g_sqsrc[n0 + tid] + mp;
    }
    __syncthreads();
}

// ----------------------- fused kernel -----------------------------
__global__ void __launch_bounds__(THREADS, 2)
sdot_fused_kernel(float* __restrict__ out, const float* __restrict__ src,
                  const float* __restrict__ tgt, const float* __restrict__ psi) {
    extern __shared__ char smem[];
    uint32_t sb = smem_u32(smem);
    const int tid = threadIdx.x, wid = tid >> 5, lane = tid & 31;
    const int wm = wid & 3, wn = wid >> 2;    // rows wm*32+[0,32), cols wn*128+[0,128) of 256
    const int q = lane >> 2, e = lane & 3;

    prep_phase(src, tgt, psi, smem, tid);
    grid_barrier(tid);

    if (tid < 32) {
        float v = 0.f;
        for (int i = lane; i < NCTAS; i += 32) v += g_psipart[i];
#pragma unroll
        for (int o = 16; o > 0; o >>= 1) v += __shfl_xor_sync(0xffffffffu, v, o);
        if (lane == 0)
            *reinterpret_cast<float*>(smem + SM_MEANPSI) = v * (1.0f / (float)M_TGT);
    }
    __syncthreads();

    const int cta = blockIdx.x;
    const int us = (int)(((long long)cta * NUNITS) / NCTAS);
    const int ue = (int)(((long long)(cta + 1) * NUNITS) / NCTAS);

    float minv[2][2] = {{CUDART_INF_F, CUDART_INF_F}, {CUDART_INF_F, CUDART_INF_F}};
    uint32_t a[2][4][4];
    int cur_nt = -1;

    load_B_chunk(sb, 0, us & (MCHUNKS - 1), tid);
    CP_COMMIT();

    for (int u = us; u < ue; ++u) {
        const int nt = u / MCHUNKS;
        const int stage = (u - us) & 1;

        if (nt != cur_nt) {
            if (cur_nt >= 0) {
                flush_and_finalize(smem, minv, cur_nt, wm, wn, q, e, tid, out);
#pragma unroll
                for (int mt = 0; mt < 2; mt++) { minv[mt][0] = CUDART_INF_F; minv[mt][1] = CUDART_INF_F; }
            }
            load_A_tile(sb, nt, tid);
            CP_COMMIT();
            CP_WAIT0();
            __syncthreads();
            load_A_frags(sb, wm, lane, a);
            cur_nt = nt;
        }

        if (u + 1 < ue) {
            load_B_chunk(sb, stage ^ 1, (u + 1) & (MCHUNKS - 1), tid);
            CP_COMMIT();
        }

        const uint32_t bbase = sb + SM_B + stage * 32768;
        const float2* cb2 = reinterpret_cast<const float2*>(smem + SM_C + stage * 1024);

        // ---- interleaved n-tile pairs: 4 independent MMA chains ----
#pragma unroll
        for (int np = 0; np < 8; np++) {
            uint32_t p0[8], p1[8];
            uint32_t nrow0 = wn * 128 + np * 16 + (lane & 7);
            uint32_t kb = (lane >> 3) * 16;
            LDSM_X4(p0[0], p0[1], p0[2], p0[3], bbase + swz128(nrow0 * 128 + kb));
            LDSM_X4(p0[4], p0[5], p0[6], p0[7], bbase + swz128(nrow0 * 128 + 64 + kb));
            LDSM_X4(p1[0], p1[1], p1[2], p1[3], bbase + swz128((nrow0 + 8) * 128 + kb));
            LDSM_X4(p1[4], p1[5], p1[6], p1[7], bbase + swz128((nrow0 + 8) * 128 + 64 + kb));

            float d00[4] = {0.f, 0.f, 0.f, 0.f};   // mt0, ntile np*2
            float d10[4] = {0.f, 0.f, 0.f, 0.f};   // mt1, ntile np*2
            float d01[4] = {0.f, 0.f, 0.f, 0.f};   // mt0, ntile np*2+1
            float d11[4] = {0.f, 0.f, 0.f, 0.f};   // mt1, ntile np*2+1

            // round-robin over 4 independent chains, k-steps outermost
            MMA16816(d00, a[0][0], p0[0], p0[1]);
            MMA16816(d10, a[1][0], p0[0], p0[1]);
            MMA16816(d01, a[0][0], p1[0], p1[1]);
            MMA16816(d11, a[1][0], p1[0], p1[1]);

            MMA16816(d00, a[0][1], p0[2], p0[3]);
            MMA16816(d10, a[1][1], p0[2], p0[3]);
            MMA16816(d01, a[0][1], p1[2], p1[3]);
            MMA16816(d11, a[1][1], p1[2], p1[3]);

            MMA16816(d00, a[0][2], p0[4], p0[5]);
            MMA16816(d10, a[1][2], p0[4], p0[5]);
            MMA16816(d01, a[0][2], p1[4], p1[5]);
            MMA16816(d11, a[1][2], p1[4], p1[5]);

            MMA16816(d00, a[0][3], p0[6], p0[7]);
            MMA16816(d10, a[1][3], p0[6], p0[7]);
            MMA16816(d01, a[0][3], p1[6], p1[7]);
            MMA16816(d11, a[1][3], p1[6], p1[7]);

            float2 cb0 = cb2[wn * 64 + np * 8 + e];
            float2 cb1 = cb2[wn * 64 + np * 8 + 4 + e];
            minv[0][0] = fminf(minv[0][0], fminf(fmaf(-2.f, d00[0], cb0.x), fmaf(-2.f, d00[1], cb0.y)));
            minv[0][1] = fminf(minv[0][1], fminf(fmaf(-2.f, d00[2], cb0.x), fmaf(-2.f, d00[3], cb0.y)));
            minv[1][0] = fminf(minv[1][0], fminf(fmaf(-2.f, d10[0], cb0.x), fmaf(-2.f, d10[1], cb0.y)));
            minv[1][1] = fminf(minv[1][1], fminf(fmaf(-2.f, d10[2], cb0.x), fmaf(-2.f, d10[3], cb0.y)));
            minv[0][0] = fminf(minv[0][0], fminf(fmaf(-2.f, d01[0], cb1.x), fmaf(-2.f, d01[1], cb1.y)));
            minv[0][1] = fminf(minv[0][1], fminf(fmaf(-2.f, d01[2], cb1.x), fmaf(-2.f, d01[3], cb1.y)));
            minv[1][0] = fminf(minv[1][0], fminf(fmaf(-2.f, d11[0], cb1.x), fmaf(-2.f, d11[1], cb1.y)));
            minv[1][1] = fminf(minv[1][1], fminf(fmaf(-2.f, d11[2], cb1.x), fmaf(-2.f, d11[3], cb1.y)));
        }

        if (u + 1 < ue) CP_WAIT0();
        __syncthreads();
    }

    flush_and_finalize(smem, minv, cur_nt, wm, wn, q, e, tid, out);
}

// ----------------------- launch ----------------------------------
extern "C" void kernel_launch(void* const* d_in, const int* in_sizes, int n_in,
                              void* d_out, int out_size) {
    const float* src = (const float*)d_in[0];   // [8192, 64]
    const float* tgt = (const float*)d_in[1];   // [32768, 64]
    const float* psi = (const float*)d_in[2];   // [32768]
    float* out = (float*)d_out;                 // [8192]

    cudaFuncSetAttribute(sdot_fused_kernel, cudaFuncAttributeMaxDynamicSharedMemorySize, SMEM_TOTAL);
    sdot_fused_kernel<<<NCTAS, THREADS, SMEM_TOTAL>>>(out, src, tgt, psi);
}

// round 15
// speedup vs baseline: 1.0838x; 1.0838x over previous
#include <cuda_runtime.h>
#include <cuda_fp16.h>
#include <math_constants.h>
#include <cstdint>

// ----------------------- problem constants -----------------------
#define N_SRC 8192
#define M_TGT 32768
#define D_DIM 64
#define BN 128
#define BM 512
#define NTILES (N_SRC / BN)         // 64
#define MCHUNKS (M_TGT / BM)        // 64
#define NUNITS (NTILES * MCHUNKS)   // 4096
#define NCTAS 148
#define THREADS 512                 // 16 warps

// ----------------------- SMEM layout -----------------------------
#define SM_A       0                // 16384
#define SM_B       16384            // 2 x 65536 = 131072
#define SM_C       147456           // 2 x 2048
#define SM_MIN     151552           // 512 floats = 2048
#define SM_FLAG    153600           // 4
#define SM_MEANPSI 153604           // 4
#define SMEM_TOTAL 153664

// ----------------------- device scratch --------------------------
__device__ __half g_src_h[N_SRC * D_DIM];
__device__ __half g_tgt_h[M_TGT * D_DIM];
__device__ float  g_c[M_TGT];
__device__ float  g_sqsrc[N_SRC];
__device__ float  g_psipart[NCTAS];
__device__ int    g_partial[N_SRC];
__device__ int    g_cnt[NTILES];
__device__ int    g_exp[NTILES];
__device__ unsigned int g_bar;       // monotonic grid barrier

// ----------------------- helpers ---------------------------------
__device__ __forceinline__ uint32_t smem_u32(const void* p) {
    uint32_t a;
    asm("{ .reg .u64 t; cvta.to.shared.u64 t, %1; cvt.u32.u64 %0, t; }" : "=r"(a) : "l"(p));
    return a;
}
__device__ __forceinline__ uint32_t swz128(uint32_t off) { return off ^ ((off >> 3) & 0x70); }

#define CP_ASYNC16(dst, src) \
    asm volatile("cp.async.cg.shared.global [%0], [%1], 16;" :: "r"((uint32_t)(dst)), "l"(src) : "memory")
#define CP_COMMIT() asm volatile("cp.async.commit_group;" ::: "memory")
#define CP_WAIT0()  asm volatile("cp.async.wait_group 0;" ::: "memory")

#define LDSM_X4(r0, r1, r2, r3, addr) \
    asm volatile("ldmatrix.sync.aligned.m8n8.x4.shared.b16 {%0,%1,%2,%3}, [%4];" \
                 : "=r"(r0), "=r"(r1), "=r"(r2), "=r"(r3) : "r"(addr))

#define MMA16816(d, a, b0, b1) \
    asm volatile("mma.sync.aligned.m16n8k16.row.col.f32.f16.f16.f32 " \
                 "{%0,%1,%2,%3},{%4,%5,%6,%7},{%8,%9},{%0,%1,%2,%3};" \
                 : "+f"((d)[0]), "+f"((d)[1]), "+f"((d)[2]), "+f"((d)[3]) \
                 : "r"((a)[0]), "r"((a)[1]), "r"((a)[2]), "r"((a)[3]), "r"(b0), "r"(b1))

__device__ __forceinline__ void atomicMinF(int* addr, float v) {
    if (v >= 0.f) atomicMin(addr, __float_as_int(v));
    else          atomicMax((unsigned int*)addr, __float_as_uint(v));
}

// ----------------------- prep phase (vectorized) ------------------
// 2 rows per warp per iteration: 16 lanes per row, float4 loads, uint2 stores.
__device__ __forceinline__ void prep_phase(const float* __restrict__ src,
                                           const float* __restrict__ tgt,
                                           const float* __restrict__ psi,
                                           char* smem, int tid) {
    const int wid = tid >> 5, lane = tid & 31;
    const int gwarp = blockIdx.x * (THREADS / 32) + wid;
    const int nwarps = NCTAS * (THREADS / 32);      // 2368
    const int hl = lane & 15;                       // lane within 16-lane row group
    const int rsel = lane >> 4;                     // 0 or 1: which row of the pair

    const int NROWS = N_SRC + M_TGT;                // 40960
    for (int r2 = gwarp * 2; r2 < NROWS; r2 += nwarps * 2) {
        int row = r2 + rsel;
        if (row < N_SRC) {
            float4 v = reinterpret_cast<const float4*>(src)[(size_t)row * 16 + hl];
            __half2 h0 = __floats2half2_rn(v.x, v.y);
            __half2 h1 = __floats2half2_rn(v.z, v.w);
            uint2 u = {*reinterpret_cast<uint32_t*>(&h0), *reinterpret_cast<uint32_t*>(&h1)};
            reinterpret_cast<uint2*>(g_src_h)[(size_t)row * 16 + hl] = u;
            float s = v.x * v.x + v.y * v.y + v.z * v.z + v.w * v.w;
#pragma unroll
            for (int o = 1; o < 16; o <<= 1) s += __shfl_xor_sync(0xffffffffu, s, o);
            if (hl == 0) g_sqsrc[row] = s;
        } else if (row < NROWS) {
            int m = row - N_SRC;
            float4 v = reinterpret_cast<const float4*>(tgt)[(size_t)m * 16 + hl];
            __half2 h0 = __floats2half2_rn(v.x, v.y);
            __half2 h1 = __floats2half2_rn(v.z, v.w);
            uint2 u = {*reinterpret_cast<uint32_t*>(&h0), *reinterpret_cast<uint32_t*>(&h1)};
            reinterpret_cast<uint2*>(g_tgt_h)[(size_t)m * 16 + hl] = u;
            float s = v.x * v.x + v.y * v.y + v.z * v.z + v.w * v.w;
#pragma unroll
            for (int o = 1; o < 16; o <<= 1) s += __shfl_xor_sync(0xffffffffu, s, o);
            if (hl == 0) g_c[m] = s - psi[m];
        }
    }

    // partial-min init
    for (int n = blockIdx.x * THREADS + tid; n < N_SRC; n += NCTAS * THREADS)
        g_partial[n] = 0x7F800000;   // +inf

    // tickets (CTA 1)
    if (blockIdx.x == 1 && tid < NTILES) {
        int nt = tid, cnt = 0;
        for (int cta = 0; cta < NCTAS; cta++) {
            int us = (int)(((long long)cta * NUNITS) / NCTAS);
            int ue = (int)(((long long)(cta + 1) * NUNITS) / NCTAS);
            if (us < (nt + 1) * MCHUNKS && ue > nt * MCHUNKS) cnt++;
        }
        g_exp[nt] = cnt;
        g_cnt[nt] = 0;
    }

    // distributed psi partial sum (deterministic)
    {
        float* red = reinterpret_cast<float*>(smem + SM_MIN);
        float s = 0.f;
        for (int i = blockIdx.x * THREADS + tid; i < M_TGT; i += NCTAS * THREADS) s += psi[i];
#pragma unroll
        for (int o = 16; o > 0; o >>= 1) s += __shfl_xor_sync(0xffffffffu, s, o);
        if ((tid & 31) == 0) red[wid] = s;
        __syncthreads();
        if (tid < 32) {
            float v = (tid < THREADS / 32) ? red[tid] : 0.f;
#pragma unroll
            for (int o = 16; o > 0; o >>= 1) v += __shfl_xor_sync(0xffffffffu, v, o);
            if (tid == 0) g_psipart[blockIdx.x] = v;
        }
        __syncthreads();
    }
}

// monotonic grid barrier: safe across graph replays
__device__ __forceinline__ void grid_barrier(int tid) {
    __syncthreads();
    if (tid == 0) {
        __threadfence();
        unsigned int base = atomicAdd(&g_bar, 1u);
        unsigned int target = (base / NCTAS + 1u) * NCTAS;
        volatile unsigned int* p = &g_bar;
        while (*p < target) { __nanosleep(64); }
    }
    __syncthreads();
    __threadfence();
}

// ----------------------- main loop pieces -------------------------
__device__ __forceinline__ void load_B_chunk(uint32_t sb, int stage, int ch, int tid) {
    const __half* p = g_tgt_h + (size_t)ch * BM * D_DIM;
    uint32_t d = sb + SM_B + stage * 65536;
#pragma unroll
    for (int j = 0; j < 8; j++) {
        int idx = j * THREADS + tid;
        int row = idx >> 3, c8 = idx & 7;
        CP_ASYNC16(d + swz128(row * 128 + c8 * 16), p + row * D_DIM + c8 * 8);
    }
    if (tid < 128)
        CP_ASYNC16(sb + SM_C + stage * 2048 + tid * 16, g_c + (size_t)ch * BM + tid * 4);
}

__device__ __forceinline__ void load_A_tile(uint32_t sb, int nt, int tid) {
    const __half* p = g_src_h + (size_t)nt * BN * D_DIM;
#pragma unroll
    for (int j = 0; j < 2; j++) {
        int idx = j * THREADS + tid;
        int row = idx >> 3, c8 = idx & 7;
        CP_ASYNC16(sb + SM_A + swz128(row * 128 + c8 * 16), p + row * D_DIM + c8 * 8);
    }
}

__device__ __forceinline__ void load_A_frags(uint32_t sb, int wm, int lane, uint32_t a[2][4][4]) {
#pragma unroll
    for (int mt = 0; mt < 2; mt++)
#pragma unroll
        for (int ks = 0; ks < 4; ks++) {
            uint32_t row = wm * 32 + mt * 16 + (lane & 15);
            uint32_t kb = ks * 32 + ((lane >> 4) & 1) * 16;
            LDSM_X4(a[mt][ks][0], a[mt][ks][1], a[mt][ks][2], a[mt][ks][3],
                    sb + SM_A + swz128(row * 128 + kb));
        }
}

__device__ __forceinline__ void flush_and_finalize(char* smem, float minv[2][2], int nt,
                                                   int wm, int wn, int q, int e, int tid,
                                                   float* __restrict__ out) {
    float* smin = reinterpret_cast<float*>(smem + SM_MIN);
#pragma unroll
    for (int mt = 0; mt < 2; mt++)
#pragma unroll
        for (int h = 0; h < 2; h++) {
            float v = minv[mt][h];
            v = fminf(v, __shfl_xor_sync(0xffffffffu, v, 1));
            v = fminf(v, __shfl_xor_sync(0xffffffffu, v, 2));
            if (e == 0) smin[wn * 128 + wm * 32 + mt * 16 + h * 8 + q] = v;
        }
    __syncthreads();
    const int n0 = nt * BN;
    if (tid < 128) {
        float v = fminf(fminf(smin[tid], smin[128 + tid]),
                        fminf(smin[256 + tid], smin[384 + tid]));
        atomicMinF(&g_partial[n0 + tid], v);
    }
    __threadfence();
    __syncthreads();
    if (tid == 0) {
        int old = atomicAdd(&g_cnt[nt], 1);
        *reinterpret_cast<int*>(smem + SM_FLAG) = (old == g_exp[nt] - 1);
    }
    __syncthreads();
    if (*reinterpret_cast<int*>(smem + SM_FLAG) && tid < 128) {
        float mp = *reinterpret_cast<float*>(smem + SM_MEANPSI);
        int bits = atomicAdd(&g_partial[n0 + tid], 0);
        out[n0 + tid] = __int_as_float(bits) + g_sqsrc[n0 + tid] + mp;
    }
    __syncthreads();
}

// ----------------------- fused kernel -----------------------------
__global__ void __launch_bounds__(THREADS, 1)
sdot_fused_kernel(float* __restrict__ out, const float* __restrict__ src,
                  const float* __restrict__ tgt, const float* __restrict__ psi) {
    extern __shared__ char smem[];
    uint32_t sb = smem_u32(smem);
    const int tid = threadIdx.x, wid = tid >> 5, lane = tid & 31;
    const int wm = wid & 3, wn = wid >> 2;    // rows wm*32+[0,32), cols wn*128+[0,128) of 512
    const int q = lane >> 2, e = lane & 3;

    // ---- phase 1: prep, then grid barrier ----
    prep_phase(src, tgt, psi, smem, tid);
    grid_barrier(tid);

    const int cta = blockIdx.x;
    const int us = (int)(((long long)cta * NUNITS) / NCTAS);
    const int ue = (int)(((long long)(cta + 1) * NUNITS) / NCTAS);

    // B prefetch FIRST (hide psi fold behind it)
    load_B_chunk(sb, 0, us & (MCHUNKS - 1), tid);
    CP_COMMIT();

    // fold distributed psi partials (fixed order -> deterministic)
    if (tid < 32) {
        float v = 0.f;
        for (int i = lane; i < NCTAS; i += 32) v += g_psipart[i];
#pragma unroll
        for (int o = 16; o > 0; o >>= 1) v += __shfl_xor_sync(0xffffffffu, v, o);
        if (lane == 0)
            *reinterpret_cast<float*>(smem + SM_MEANPSI) = v * (1.0f / (float)M_TGT);
    }
    __syncthreads();

    // ---- phase 2: persistent HMMA + min ----
    float minv[2][2] = {{CUDART_INF_F, CUDART_INF_F}, {CUDART_INF_F, CUDART_INF_F}};
    uint32_t a[2][4][4];
    int cur_nt = -1;

    for (int u = us; u < ue; ++u) {
        const int nt = u / MCHUNKS;
        const int stage = (u - us) & 1;

        if (nt != cur_nt) {
            if (cur_nt >= 0) {
                flush_and_finalize(smem, minv, cur_nt, wm, wn, q, e, tid, out);
#pragma unroll
                for (int mt = 0; mt < 2; mt++) { minv[mt][0] = CUDART_INF_F; minv[mt][1] = CUDART_INF_F; }
            }
            load_A_tile(sb, nt, tid);
            CP_COMMIT();
            CP_WAIT0();
            __syncthreads();
            load_A_frags(sb, wm, lane, a);
            cur_nt = nt;
        }

        if (u + 1 < ue) {
            load_B_chunk(sb, stage ^ 1, (u + 1) & (MCHUNKS - 1), tid);
            CP_COMMIT();
        }

        const uint32_t bbase = sb + SM_B + stage * 65536;
        const float2* cb2 = reinterpret_cast<const float2*>(smem + SM_C + stage * 2048);
#pragma unroll
        for (int ntile = 0; ntile < 16; ntile++) {
            uint32_t b0[4], b1[4];
            uint32_t nrow = wn * 128 + ntile * 8 + (lane & 7);
            uint32_t kb = (lane >> 3) * 16;
            LDSM_X4(b0[0], b0[1], b0[2], b0[3], bbase + swz128(nrow * 128 + kb));
            LDSM_X4(b1[0], b1[1], b1[2], b1[3], bbase + swz128(nrow * 128 + 64 + kb));

            float d0[4] = {0.f, 0.f, 0.f, 0.f};
            float d1[4] = {0.f, 0.f, 0.f, 0.f};
            MMA16816(d0, a[0][0], b0[0], b0[1]);
            MMA16816(d1, a[1][0], b0[0], b0[1]);
            MMA16816(d0, a[0][1], b0[2], b0[3]);
            MMA16816(d1, a[1][1], b0[2], b0[3]);
            MMA16816(d0, a[0][2], b1[0], b1[1]);
            MMA16816(d1, a[1][2], b1[0], b1[1]);
            MMA16816(d0, a[0][3], b1[2], b1[3]);
            MMA16816(d1, a[1][3], b1[2], b1[3]);

            float2 cb = cb2[wn * 64 + ntile * 4 + e];
            minv[0][0] = fminf(minv[0][0], fminf(fmaf(-2.f, d0[0], cb.x), fmaf(-2.f, d0[1], cb.y)));
            minv[0][1] = fminf(minv[0][1], fminf(fmaf(-2.f, d0[2], cb.x), fmaf(-2.f, d0[3], cb.y)));
            minv[1][0] = fminf(minv[1][0], fminf(fmaf(-2.f, d1[0], cb.x), fmaf(-2.f, d1[1], cb.y)));
            minv[1][1] = fminf(minv[1][1], fminf(fmaf(-2.f, d1[2], cb.x), fmaf(-2.f, d1[3], cb.y)));
        }

        if (u + 1 < ue) CP_WAIT0();
        __syncthreads();
    }

    flush_and_finalize(smem, minv, cur_nt, wm, wn, q, e, tid, out);
}

// ----------------------- launch ----------------------------------
extern "C" void kernel_launch(void* const* d_in, const int* in_sizes, int n_in,
                              void* d_out, int out_size) {
    const float* src = (const float*)d_in[0];   // [8192, 64]
    const float* tgt = (const float*)d_in[1];   // [32768, 64]
    const float* psi = (const float*)d_in[2];   // [32768]
    float* out = (float*)d_out;                 // [8192]

    cudaFuncSetAttribute(sdot_fused_kernel, cudaFuncAttributeMaxDynamicSharedMemorySize, SMEM_TOTAL);
    sdot_fused_kernel<<<NCTAS, THREADS, SMEM_TOTAL>>>(out, src, tgt, psi);
}

// round 16
// speedup vs baseline: 1.1020x; 1.0168x over previous
#include <cuda_runtime.h>
#include <cuda_fp16.h>
#include <math_constants.h>
#include <cstdint>

// ----------------------- problem constants -----------------------
#define N_SRC 8192
#define M_TGT 32768
#define D_DIM 64
#define BN 128
#define BM 512
#define NTILES (N_SRC / BN)         // 64
#define MCHUNKS (M_TGT / BM)        // 64
#define NUNITS (NTILES * MCHUNKS)   // 4096
#define NCTAS 148
#define THREADS 512                 // 16 warps

// ----------------------- SMEM layout -----------------------------
#define SM_A       0                // 16384
#define SM_B       16384            // 2 x 65536 = 131072
#define SM_C       147456           // 2 x 2048
#define SM_MIN     151552           // 512 floats = 2048
#define SM_FLAG    153600           // 4
#define SM_MEANPSI 153604           // 4
#define SMEM_TOTAL 153664

// ----------------------- device scratch --------------------------
__device__ __half g_src_h[N_SRC * D_DIM];
__device__ __half g_tgt_h[M_TGT * D_DIM];
__device__ float  g_c[M_TGT];
__device__ float  g_sqsrc[N_SRC];
__device__ float  g_psipart[NCTAS];
__device__ int    g_partial[N_SRC];
__device__ int    g_cnt[NTILES];
__device__ int    g_exp[NTILES];
__device__ unsigned int g_bar;       // monotonic grid barrier

// ----------------------- helpers ---------------------------------
__device__ __forceinline__ uint32_t smem_u32(const void* p) {
    uint32_t a;
    asm("{ .reg .u64 t; cvta.to.shared.u64 t, %1; cvt.u32.u64 %0, t; }" : "=r"(a) : "l"(p));
    return a;
}
__device__ __forceinline__ uint32_t swz128(uint32_t off) { return off ^ ((off >> 3) & 0x70); }

#define CP_ASYNC16(dst, src) \
    asm volatile("cp.async.cg.shared.global [%0], [%1], 16;" :: "r"((uint32_t)(dst)), "l"(src) : "memory")
#define CP_COMMIT() asm volatile("cp.async.commit_group;" ::: "memory")
#define CP_WAIT0()  asm volatile("cp.async.wait_group 0;" ::: "memory")

#define LDSM_X4(r0, r1, r2, r3, addr) \
    asm volatile("ldmatrix.sync.aligned.m8n8.x4.shared.b16 {%0,%1,%2,%3}, [%4];" \
                 : "=r"(r0), "=r"(r1), "=r"(r2), "=r"(r3) : "r"(addr))

#define MMA16816(d, a, b0, b1) \
    asm volatile("mma.sync.aligned.m16n8k16.row.col.f32.f16.f16.f32 " \
                 "{%0,%1,%2,%3},{%4,%5,%6,%7},{%8,%9},{%0,%1,%2,%3};" \
                 : "+f"((d)[0]), "+f"((d)[1]), "+f"((d)[2]), "+f"((d)[3]) \
                 : "r"((a)[0]), "r"((a)[1]), "r"((a)[2]), "r"((a)[3]), "r"(b0), "r"(b1))

__device__ __forceinline__ void atomicMinF(int* addr, float v) {
    if (v >= 0.f) atomicMin(addr, __float_as_int(v));
    else          atomicMax((unsigned int*)addr, __float_as_uint(v));
}

// ----------------------- prep phase (vectorized, psi fused) -------
__device__ __forceinline__ void prep_phase(const float* __restrict__ src,
                                           const float* __restrict__ tgt,
                                           const float* __restrict__ psi,
                                           char* smem, int tid) {
    const int wid = tid >> 5, lane = tid & 31;
    const int gwarp = blockIdx.x * (THREADS / 32) + wid;
    const int nwarps = NCTAS * (THREADS / 32);      // 2368
    const int hl = lane & 15;
    const int rsel = lane >> 4;

    float s_psi = 0.f;                              // fused psi partial

    const int NROWS = N_SRC + M_TGT;                // 40960
    for (int r2 = gwarp * 2; r2 < NROWS; r2 += nwarps * 2) {
        int row = r2 + rsel;
        if (row < N_SRC) {
            float4 v = reinterpret_cast<const float4*>(src)[(size_t)row * 16 + hl];
            __half2 h0 = __floats2half2_rn(v.x, v.y);
            __half2 h1 = __floats2half2_rn(v.z, v.w);
            uint2 u = {*reinterpret_cast<uint32_t*>(&h0), *reinterpret_cast<uint32_t*>(&h1)};
            reinterpret_cast<uint2*>(g_src_h)[(size_t)row * 16 + hl] = u;
            float s = v.x * v.x + v.y * v.y + v.z * v.z + v.w * v.w;
#pragma unroll
            for (int o = 1; o < 16; o <<= 1) s += __shfl_xor_sync(0xffffffffu, s, o);
            if (hl == 0) g_sqsrc[row] = s;
        } else if (row < NROWS) {
            int m = row - N_SRC;
            float4 v = reinterpret_cast<const float4*>(tgt)[(size_t)m * 16 + hl];
            __half2 h0 = __floats2half2_rn(v.x, v.y);
            __half2 h1 = __floats2half2_rn(v.z, v.w);
            uint2 u = {*reinterpret_cast<uint32_t*>(&h0), *reinterpret_cast<uint32_t*>(&h1)};
            reinterpret_cast<uint2*>(g_tgt_h)[(size_t)m * 16 + hl] = u;
            float s = v.x * v.x + v.y * v.y + v.z * v.z + v.w * v.w;
#pragma unroll
            for (int o = 1; o < 16; o <<= 1) s += __shfl_xor_sync(0xffffffffu, s, o);
            if (hl == 0) {
                float p = psi[m];
                g_c[m] = s - p;
                s_psi += p;            // each m counted exactly once globally
            }
        }
    }

    // partial-min init
    for (int n = blockIdx.x * THREADS + tid; n < N_SRC; n += NCTAS * THREADS)
        g_partial[n] = 0x7F800000;   // +inf

    // tickets (CTA 1)
    if (blockIdx.x == 1 && tid < NTILES) {
        int nt = tid, cnt = 0;
        for (int cta = 0; cta < NCTAS; cta++) {
            int us = (int)(((long long)cta * NUNITS) / NCTAS);
            int ue = (int)(((long long)(cta + 1) * NUNITS) / NCTAS);
            if (us < (nt + 1) * MCHUNKS && ue > nt * MCHUNKS) cnt++;
        }
        g_exp[nt] = cnt;
        g_cnt[nt] = 0;
    }

    // block-reduce the fused psi partial (deterministic fixed tree)
    {
        float* red = reinterpret_cast<float*>(smem + SM_MIN);
        float s = s_psi;
#pragma unroll
        for (int o = 16; o > 0; o >>= 1) s += __shfl_xor_sync(0xffffffffu, s, o);
        if (lane == 0) red[wid] = s;
        __syncthreads();
        if (tid < 32) {
            float v = (tid < THREADS / 32) ? red[tid] : 0.f;
#pragma unroll
            for (int o = 16; o > 0; o >>= 1) v += __shfl_xor_sync(0xffffffffu, v, o);
            if (tid == 0) g_psipart[blockIdx.x] = v;
        }
        __syncthreads();
    }
}

// monotonic grid barrier: safe across graph replays
__device__ __forceinline__ void grid_barrier(int tid) {
    __syncthreads();
    if (tid == 0) {
        __threadfence();
        unsigned int base = atomicAdd(&g_bar, 1u);
        unsigned int target = (base / NCTAS + 1u) * NCTAS;
        volatile unsigned int* p = &g_bar;
        while (*p < target) { __nanosleep(64); }
    }
    __syncthreads();
    __threadfence();
}

// ----------------------- main loop pieces -------------------------
__device__ __forceinline__ void load_B_chunk(uint32_t sb, int stage, int ch, int tid) {
    const __half* p = g_tgt_h + (size_t)ch * BM * D_DIM;
    uint32_t d = sb + SM_B + stage * 65536;
#pragma unroll
    for (int j = 0; j < 8; j++) {
        int idx = j * THREADS + tid;
        int row = idx >> 3, c8 = idx & 7;
        CP_ASYNC16(d + swz128(row * 128 + c8 * 16), p + row * D_DIM + c8 * 8);
    }
    if (tid < 128)
        CP_ASYNC16(sb + SM_C + stage * 2048 + tid * 16, g_c + (size_t)ch * BM + tid * 4);
}

__device__ __forceinline__ void load_A_tile(uint32_t sb, int nt, int tid) {
    const __half* p = g_src_h + (size_t)nt * BN * D_DIM;
#pragma unroll
    for (int j = 0; j < 2; j++) {
        int idx = j * THREADS + tid;
        int row = idx >> 3, c8 = idx & 7;
        CP_ASYNC16(sb + SM_A + swz128(row * 128 + c8 * 16), p + row * D_DIM + c8 * 8);
    }
}

__device__ __forceinline__ void load_A_frags(uint32_t sb, int wm, int lane, uint32_t a[2][4][4]) {
#pragma unroll
    for (int mt = 0; mt < 2; mt++)
#pragma unroll
        for (int ks = 0; ks < 4; ks++) {
            uint32_t row = wm * 32 + mt * 16 + (lane & 15);
            uint32_t kb = ks * 32 + ((lane >> 4) & 1) * 16;
            LDSM_X4(a[mt][ks][0], a[mt][ks][1], a[mt][ks][2], a[mt][ks][3],
                    sb + SM_A + swz128(row * 128 + kb));
        }
}

__device__ __forceinline__ void flush_and_finalize(char* smem, float minv[2][2], int nt,
                                                   int wm, int wn, int q, int e, int tid,
                                                   float* __restrict__ out) {
    float* smin = reinterpret_cast<float*>(smem + SM_MIN);
#pragma unroll
    for (int mt = 0; mt < 2; mt++)
#pragma unroll
        for (int h = 0; h < 2; h++) {
            float v = minv[mt][h];
            v = fminf(v, __shfl_xor_sync(0xffffffffu, v, 1));
            v = fminf(v, __shfl_xor_sync(0xffffffffu, v, 2));
            if (e == 0) smin[wn * 128 + wm * 32 + mt * 16 + h * 8 + q] = v;
        }
    __syncthreads();
    const int n0 = nt * BN;
    if (tid < 128) {
        float v = fminf(fminf(smin[tid], smin[128 + tid]),
                        fminf(smin[256 + tid], smin[384 + tid]));
        atomicMinF(&g_partial[n0 + tid], v);
    }
    __threadfence();
    __syncthreads();
    if (tid == 0) {
        int old = atomicAdd(&g_cnt[nt], 1);
        *reinterpret_cast<int*>(smem + SM_FLAG) = (old == g_exp[nt] - 1);
    }
    __syncthreads();
    if (*reinterpret_cast<int*>(smem + SM_FLAG) && tid < 128) {
        float mp = *reinterpret_cast<float*>(smem + SM_MEANPSI);
        int bits = atomicAdd(&g_partial[n0 + tid], 0);
        out[n0 + tid] = __int_as_float(bits) + g_sqsrc[n0 + tid] + mp;
    }
    __syncthreads();
}

// ----------------------- fused kernel -----------------------------
__global__ void __launch_bounds__(THREADS, 1)
sdot_fused_kernel(float* __restrict__ out, const float* __restrict__ src,
                  const float* __restrict__ tgt, const float* __restrict__ psi) {
    extern __shared__ char smem[];
    uint32_t sb = smem_u32(smem);
    const int tid = threadIdx.x, wid = tid >> 5, lane = tid & 31;
    const int wm = wid & 3, wn = wid >> 2;    // rows wm*32+[0,32), cols wn*128+[0,128) of 512
    const int q = lane >> 2, e = lane & 3;

    // ---- phase 1: prep, then grid barrier ----
    prep_phase(src, tgt, psi, smem, tid);
    grid_barrier(tid);

    const int cta = blockIdx.x;
    const int us = (int)(((long long)cta * NUNITS) / NCTAS);
    const int ue = (int)(((long long)(cta + 1) * NUNITS) / NCTAS);

    // B prefetch FIRST (hide psi fold behind it)
    load_B_chunk(sb, 0, us & (MCHUNKS - 1), tid);
    CP_COMMIT();

    // fold distributed psi partials (fixed order -> deterministic)
    if (tid < 32) {
        float v = 0.f;
        for (int i = lane; i < NCTAS; i += 32) v += g_psipart[i];
#pragma unroll
        for (int o = 16; o > 0; o >>= 1) v += __shfl_xor_sync(0xffffffffu, v, o);
        if (lane == 0)
            *reinterpret_cast<float*>(smem + SM_MEANPSI) = v * (1.0f / (float)M_TGT);
    }
    __syncthreads();

    // ---- phase 2: persistent HMMA + min ----
    float minv[2][2] = {{CUDART_INF_F, CUDART_INF_F}, {CUDART_INF_F, CUDART_INF_F}};
    uint32_t a[2][4][4];
    int cur_nt = -1;

    for (int u = us; u < ue; ++u) {
        const int nt = u / MCHUNKS;
        const int stage = (u - us) & 1;

        if (nt != cur_nt) {
            if (cur_nt >= 0) {
                flush_and_finalize(smem, minv, cur_nt, wm, wn, q, e, tid, out);
#pragma unroll
                for (int mt = 0; mt < 2; mt++) { minv[mt][0] = CUDART_INF_F; minv[mt][1] = CUDART_INF_F; }
            }
            load_A_tile(sb, nt, tid);
            CP_COMMIT();
            CP_WAIT0();
            __syncthreads();
            load_A_frags(sb, wm, lane, a);
            cur_nt = nt;
        }

        if (u + 1 < ue) {
            load_B_chunk(sb, stage ^ 1, (u + 1) & (MCHUNKS - 1), tid);
            CP_COMMIT();
        }

        const uint32_t bbase = sb + SM_B + stage * 65536;
        const float2* cb2 = reinterpret_cast<const float2*>(smem + SM_C + stage * 2048);
#pragma unroll
        for (int ntile = 0; ntile < 16; ntile++) {
            uint32_t b0[4], b1[4];
            uint32_t nrow = wn * 128 + ntile * 8 + (lane & 7);
            uint32_t kb = (lane >> 3) * 16;
            LDSM_X4(b0[0], b0[1], b0[2], b0[3], bbase + swz128(nrow * 128 + kb));
            LDSM_X4(b1[0], b1[1], b1[2], b1[3], bbase + swz128(nrow * 128 + 64 + kb));

            float d0[4] = {0.f, 0.f, 0.f, 0.f};
            float d1[4] = {0.f, 0.f, 0.f, 0.f};
            MMA16816(d0, a[0][0], b0[0], b0[1]);
            MMA16816(d1, a[1][0], b0[0], b0[1]);
            MMA16816(d0, a[0][1], b0[2], b0[3]);
            MMA16816(d1, a[1][1], b0[2], b0[3]);
            MMA16816(d0, a[0][2], b1[0], b1[1]);
            MMA16816(d1, a[1][2], b1[0], b1[1]);
            MMA16816(d0, a[0][3], b1[2], b1[3]);
            MMA16816(d1, a[1][3], b1[2], b1[3]);

            float2 cb = cb2[wn * 64 + ntile * 4 + e];
            minv[0][0] = fminf(minv[0][0], fminf(fmaf(-2.f, d0[0], cb.x), fmaf(-2.f, d0[1], cb.y)));
            minv[0][1] = fminf(minv[0][1], fminf(fmaf(-2.f, d0[2], cb.x), fmaf(-2.f, d0[3], cb.y)));
            minv[1][0] = fminf(minv[1][0], fminf(fmaf(-2.f, d1[0], cb.x), fmaf(-2.f, d1[1], cb.y)));
            minv[1][1] = fminf(minv[1][1], fminf(fmaf(-2.f, d1[2], cb.x), fmaf(-2.f, d1[3], cb.y)));
        }

        if (u + 1 < ue) CP_WAIT0();
        __syncthreads();
    }

    flush_and_finalize(smem, minv, cur_nt, wm, wn, q, e, tid, out);
}

// ----------------------- launch ----------------------------------
extern "C" void kernel_launch(void* const* d_in, const int* in_sizes, int n_in,
                              void* d_out, int out_size) {
    const float* src = (const float*)d_in[0];   // [8192, 64]
    const float* tgt = (const float*)d_in[1];   // [32768, 64]
    const float* psi = (const float*)d_in[2];   // [32768]
    float* out = (float*)d_out;                 // [8192]

    cudaFuncSetAttribute(sdot_fused_kernel, cudaFuncAttributeMaxDynamicSharedMemorySize, SMEM_TOTAL);
    sdot_fused_kernel<<<NCTAS, THREADS, SMEM_TOTAL>>>(out, src, tgt, psi);
}